// round 8
// baseline (speedup 1.0000x reference)
#include <cuda_runtime.h>
#include <math.h>
#include <stdint.h>

#define BATCH 8
#define C1    192
#define C3    576
#define HEADS 4
#define CHD   48
#define HH    128
#define WW    128
#define NPIX  16384
#define EPSV  1e-5f
#define NSPLIT 32

// ---------------- scratch (static device allocations) -----------------------
__device__ float g_bufA[BATCH * C3 * NPIX];
__device__ float g_bufB[BATCH * C3 * NPIX];
__device__ float g_bufD[BATCH * C1 * NPIX];
__device__ float g_sumsq[BATCH * 2 * C1];
__device__ float g_attn_part[32 * NSPLIT * CHD * CHD];
__device__ float g_attn[32 * CHD * CHD];
__device__ float g_M[BATCH * C1 * C1];      // fused proj_w @ blockdiag(attn)
__device__ float g_mu[BATCH * NPIX];        // per-pixel LN mean
__device__ float g_inv[BATCH * NPIX];       // per-pixel LN rstd
__device__ float g_W2[C3 * C1];             // qkv_w * ln1_w (folded)
__device__ float g_S[C3];                   // row sums of g_W2
__device__ float g_T[C3];                   // qkv_w@ln1_b + qkv_b

// ---------------- per-pixel LN stats ----------------------------------------
__global__ void __launch_bounds__(256) stats_kernel(
    const float* __restrict__ x, float* __restrict__ mu_o, float* __restrict__ inv_o)
{
    int idx = blockIdx.x * 256 + threadIdx.x;
    int bb = idx >> 14;
    int p  = idx & (NPIX - 1);
    const float* xp = x + (size_t)bb * C1 * NPIX + p;
    float s = 0.f, s2 = 0.f;
    #pragma unroll 4
    for (int c = 0; c < C1; c++) {
        float v = xp[(size_t)c * NPIX];
        s += v; s2 = fmaf(v, v, s2);
    }
    float mu  = s * (1.f / C1);
    float var = fmaxf(s2 * (1.f / C1) - mu * mu, 0.f);
    mu_o[idx]  = mu;
    inv_o[idx] = rsqrtf(var + EPSV);
}

// ---------------- fold ln1 into qkv weights ---------------------------------
__global__ void __launch_bounds__(192) prep_qkv_kernel(
    const float* __restrict__ qw, const float* __restrict__ qb,
    const float* __restrict__ lw, const float* __restrict__ lb)
{
    int oc = blockIdx.x * 192 + threadIdx.x;
    if (oc >= C3) return;
    const float* wr = qw + (size_t)oc * C1;
    float s = 0.f, t = 0.f;
    for (int c = 0; c < C1; c++) {
        float w2 = wr[c] * lw[c];
        g_W2[(size_t)oc * C1 + c] = w2;
        s += w2;
        t = fmaf(wr[c], lb[c], t);
    }
    g_S[oc] = s;
    g_T[oc] = t + qb[oc];
}

// ---------------- tf32 tensor-core GEMM with cp.async double buffering ------
// FUSE: 0 = bias, 1 = bias+GELU, 2 = bias+residual, 3 = LN-folded (bias=T, Svec=S)
#define ASTRIDE 36
#define BSTRIDE 264
#define ASTAGE  (64 * ASTRIDE)
#define BSTAGE  (32 * BSTRIDE)
#define GEMM_SMEM ((2 * (ASTAGE + BSTAGE)) * 4)

__device__ __forceinline__ void mma_tf32(float* c, const uint32_t* a, const uint32_t* b) {
    asm volatile(
        "mma.sync.aligned.m16n8k8.row.col.f32.tf32.tf32.f32 "
        "{%0,%1,%2,%3}, {%4,%5,%6,%7}, {%8,%9}, {%0,%1,%2,%3};\n"
        : "+f"(c[0]), "+f"(c[1]), "+f"(c[2]), "+f"(c[3])
        : "r"(a[0]), "r"(a[1]), "r"(a[2]), "r"(a[3]), "r"(b[0]), "r"(b[1]));
}
__device__ __forceinline__ void cp16(void* s, const void* g) {
    uint32_t sa = (uint32_t)__cvta_generic_to_shared(s);
    asm volatile("cp.async.cg.shared.global [%0], [%1], 16;\n" :: "r"(sa), "l"(g));
}

template<int FUSE>
__global__ void __launch_bounds__(256) gemm_tf32_kernel(
    const float* __restrict__ in, float* __restrict__ out,
    const float* __restrict__ W, const float* __restrict__ bias,
    const float* __restrict__ resid, int M, int K,
    int in_bstride, int in_coff, int w_bstride,
    const float* __restrict__ Svec, const float* __restrict__ lnmu,
    const float* __restrict__ lninv)
{
    extern __shared__ float dsm[];
    float* As = dsm;
    float* Bs = dsm + 2 * ASTAGE;

    const int tid  = threadIdx.x;
    const int lane = tid & 31;
    const int wrp  = tid >> 5;
    const int n0   = blockIdx.x * 256;
    const int m0   = blockIdx.y * 64;
    const int bb   = blockIdx.z;
    const float* inb = in + ((size_t)bb * in_bstride + in_coff) * NPIX + n0;
    const float* Wb  = W + (size_t)bb * w_bstride;

    const int am = tid >> 2;
    const int ak = (tid & 3) * 8;

    float acc[4][4][4];
    #pragma unroll
    for (int mt = 0; mt < 4; mt++)
        #pragma unroll
        for (int nt = 0; nt < 4; nt++)
            #pragma unroll
            for (int i = 0; i < 4; i++) acc[mt][nt][i] = 0.f;

    auto load_stage = [&](int k0, int st) {
        const float* wr = Wb + (size_t)(m0 + am) * K + k0 + ak;
        float* ad = As + st * ASTAGE + am * ASTRIDE + ak;
        cp16(ad, wr);
        cp16(ad + 4, wr + 4);
        #pragma unroll
        for (int i = 0; i < 8; i++) {
            int l  = tid + i * 256;
            int r  = l >> 6;
            int c4 = (l & 63) * 4;
            cp16(Bs + st * BSTAGE + r * BSTRIDE + c4,
                 inb + (size_t)(k0 + r) * NPIX + c4);
        }
    };

    load_stage(0, 0);
    asm volatile("cp.async.commit_group;\n" ::);

    for (int k0 = 0; k0 < K; k0 += 32) {
        int st = (k0 >> 5) & 1;
        if (k0 + 32 < K) {
            load_stage(k0 + 32, st ^ 1);
            asm volatile("cp.async.commit_group;\n" ::);
            asm volatile("cp.async.wait_group 1;\n" ::);
        } else {
            asm volatile("cp.async.wait_all;\n" ::);
        }
        __syncthreads();

        const uint32_t* Au = (const uint32_t*)(As + st * ASTAGE);
        const uint32_t* Bu = (const uint32_t*)(Bs + st * BSTAGE);
        #pragma unroll
        for (int kk = 0; kk < 32; kk += 8) {
            const int kr   = kk + (lane & 3);
            const int mrow = lane >> 2;
            uint32_t a[4][4], b[4][2];
            #pragma unroll
            for (int mt = 0; mt < 4; mt++) {
                int mb = mt * 16 + mrow;
                a[mt][0] = Au[mb * ASTRIDE + kr];
                a[mt][1] = Au[(mb + 8) * ASTRIDE + kr];
                a[mt][2] = Au[mb * ASTRIDE + kr + 4];
                a[mt][3] = Au[(mb + 8) * ASTRIDE + kr + 4];
            }
            #pragma unroll
            for (int nt = 0; nt < 4; nt++) {
                int nc = wrp * 32 + nt * 8 + (lane >> 2);
                b[nt][0] = Bu[kr * BSTRIDE + nc];
                b[nt][1] = Bu[(kr + 4) * BSTRIDE + nc];
            }
            #pragma unroll
            for (int mt = 0; mt < 4; mt++)
                #pragma unroll
                for (int nt = 0; nt < 4; nt++)
                    mma_tf32(acc[mt][nt], a[mt], b[nt]);
        }
        __syncthreads();
    }

    #pragma unroll
    for (int mt = 0; mt < 4; mt++) {
        int r0 = m0 + mt * 16 + (lane >> 2);
        int r1 = r0 + 8;
        float bv0 = __ldg(&bias[r0]);
        float bv1 = __ldg(&bias[r1]);
        float sv0 = 0.f, sv1 = 0.f;
        if (FUSE == 3) { sv0 = __ldg(&Svec[r0]); sv1 = __ldg(&Svec[r1]); }
        float* o0 = out + ((size_t)bb * M + r0) * NPIX + n0;
        float* o1 = out + ((size_t)bb * M + r1) * NPIX + n0;
        #pragma unroll
        for (int nt = 0; nt < 4; nt++) {
            int col = wrp * 32 + nt * 8 + (lane & 3) * 2;
            float v0, v1, v2, v3;
            if (FUSE == 3) {
                float2 mu2  = *(const float2*)(lnmu  + (size_t)bb * NPIX + n0 + col);
                float2 inv2 = *(const float2*)(lninv + (size_t)bb * NPIX + n0 + col);
                v0 = fmaf(acc[mt][nt][0] - mu2.x * sv0, inv2.x, bv0);
                v1 = fmaf(acc[mt][nt][1] - mu2.y * sv0, inv2.y, bv0);
                v2 = fmaf(acc[mt][nt][2] - mu2.x * sv1, inv2.x, bv1);
                v3 = fmaf(acc[mt][nt][3] - mu2.y * sv1, inv2.y, bv1);
            } else {
                v0 = acc[mt][nt][0] + bv0;
                v1 = acc[mt][nt][1] + bv0;
                v2 = acc[mt][nt][2] + bv1;
                v3 = acc[mt][nt][3] + bv1;
            }
            if (FUSE == 1) {
                v0 = 0.5f * v0 * (1.f + erff(v0 * 0.70710678118654752f));
                v1 = 0.5f * v1 * (1.f + erff(v1 * 0.70710678118654752f));
                v2 = 0.5f * v2 * (1.f + erff(v2 * 0.70710678118654752f));
                v3 = 0.5f * v3 * (1.f + erff(v3 * 0.70710678118654752f));
            }
            if (FUSE == 2) {
                const float* rr0 = resid + ((size_t)bb * M + r0) * NPIX + n0;
                const float* rr1 = resid + ((size_t)bb * M + r1) * NPIX + n0;
                float2 q0 = *(const float2*)(rr0 + col);
                float2 q1 = *(const float2*)(rr1 + col);
                v0 += q0.x; v1 += q0.y; v2 += q1.x; v3 += q1.y;
            }
            *(float2*)(o0 + col) = make_float2(v0, v1);
            *(float2*)(o1 + col) = make_float2(v2, v3);
        }
    }
}

// ---------------- depthwise / grouped 3x3 conv, pad 1, 4 px/thread ----------
// LNF: apply (v - mu_p)*inv_p*lnw[ci] + lnb[ci] to every loaded input value
template<int RATIO, bool SUMSQ, bool LNF>
__global__ void __launch_bounds__(256) dwconv_kernel(
    const float* __restrict__ in, float* __restrict__ out,
    const float* __restrict__ wt, const float* __restrict__ bias,
    const float* __restrict__ prompt,
    const float* __restrict__ mu_a, const float* __restrict__ inv_a,
    const float* __restrict__ lnw, const float* __restrict__ lnb)
{
    int idx  = blockIdx.x * 256 + threadIdx.x;
    int q    = idx & 4095;
    int rest = idx >> 12;
    int c    = rest % C3;
    int bb   = rest / C3;
    int p  = q << 2;
    int y  = p >> 7, x0 = p & 127;

    const int ci = c / RATIO;
    const float* ip = in + ((size_t)bb * (C3 / RATIO) + ci) * NPIX;
    const float* wp = wt + c * 9;
    const float* mup = LNF ? (mu_a  + (size_t)bb * NPIX) : nullptr;
    const float* ivp = LNF ? (inv_a + (size_t)bb * NPIX) : nullptr;
    float lw = 0.f, lb = 0.f;
    if (LNF) { lw = __ldg(&lnw[ci]); lb = __ldg(&lnb[ci]); }

    float w[9];
    #pragma unroll
    for (int i = 0; i < 9; i++) w[i] = __ldg(&wp[i]);

    float bv = bias[c];
    if (prompt != nullptr)
        bv += prompt[((c % C1) / CHD) * CHD + (c % CHD)];
    float o0 = bv, o1 = bv, o2 = bv, o3 = bv;

    #pragma unroll
    for (int dy = -1; dy <= 1; dy++) {
        int yy = y + dy;
        if ((unsigned)yy < (unsigned)HH) {
            const float* rp = ip + yy * WW;
            float4 m = *(const float4*)(rp + x0);
            float L = (x0 > 0)   ? rp[x0 - 1] : 0.f;
            float R = (x0 < 124) ? rp[x0 + 4] : 0.f;
            if (LNF) {
                int rb = yy * WW + x0;
                float4 m4 = *(const float4*)(mup + rb);
                float4 i4 = *(const float4*)(ivp + rb);
                m.x = fmaf((m.x - m4.x) * i4.x, lw, lb);
                m.y = fmaf((m.y - m4.y) * i4.y, lw, lb);
                m.z = fmaf((m.z - m4.z) * i4.z, lw, lb);
                m.w = fmaf((m.w - m4.w) * i4.w, lw, lb);
                if (x0 > 0)
                    L = fmaf((L - mup[rb - 1]) * ivp[rb - 1], lw, lb);
                if (x0 < 124)
                    R = fmaf((R - mup[rb + 4]) * ivp[rb + 4], lw, lb);
            }
            float w0 = w[(dy + 1) * 3 + 0];
            float w1 = w[(dy + 1) * 3 + 1];
            float w2 = w[(dy + 1) * 3 + 2];
            o0 = fmaf(w0, L,   fmaf(w1, m.x, fmaf(w2, m.y, o0)));
            o1 = fmaf(w0, m.x, fmaf(w1, m.y, fmaf(w2, m.z, o1)));
            o2 = fmaf(w0, m.y, fmaf(w1, m.z, fmaf(w2, m.w, o2)));
            o3 = fmaf(w0, m.z, fmaf(w1, m.w, fmaf(w2, R,   o3)));
        }
    }
    *(float4*)(out + ((size_t)bb * C3 + c) * NPIX + p) = make_float4(o0, o1, o2, o3);

    if (SUMSQ) {
        float ssq = o0 * o0 + o1 * o1 + o2 * o2 + o3 * o3;
        __shared__ float red[8];
        #pragma unroll
        for (int off = 16; off > 0; off >>= 1)
            ssq += __shfl_down_sync(0xffffffffu, ssq, off);
        if ((threadIdx.x & 31) == 0) red[threadIdx.x >> 5] = ssq;
        __syncthreads();
        if (threadIdx.x == 0 && c < 2 * C1) {
            float t = 0.f;
            #pragma unroll
            for (int wv = 0; wv < 8; wv++) t += red[wv];
            atomicAdd(&g_sumsq[bb * 2 * C1 + c], t);
        }
    }
}

// ---------------- QK^T partial GEMM (48x48, split-K over spatial) -----------
__global__ void __launch_bounds__(256) qk_partial_kernel(const float* __restrict__ qkv)
{
    const int bh = blockIdx.x, split = blockIdx.y;
    const int bb = bh >> 2, h = bh & 3;
    const int CSPL = NPIX / NSPLIT;   // 512
    const float* qb = qkv + ((size_t)bb * C3 + h * CHD) * NPIX + split * CSPL;
    const float* kb = qkv + ((size_t)bb * C3 + C1 + h * CHD) * NPIX + split * CSPL;
    __shared__ float sq[CHD][33];
    __shared__ float sk[CHD][33];
    const int tid = threadIdx.x;
    const int c0 = (tid >> 4) * 3, d0 = (tid & 15) * 3;
    float acc[3][3] = {};

    for (int n0 = 0; n0 < CSPL; n0 += 32) {
        for (int i = tid; i < CHD * 32; i += 256) {
            int c = i >> 5, j = i & 31;
            sq[c][j] = qb[(size_t)c * NPIX + n0 + j];
            sk[c][j] = kb[(size_t)c * NPIX + n0 + j];
        }
        __syncthreads();
        #pragma unroll
        for (int j = 0; j < 32; j++) {
            float q0 = sq[c0][j], q1 = sq[c0 + 1][j], q2 = sq[c0 + 2][j];
            float k0v = sk[d0][j], k1v = sk[d0 + 1][j], k2v = sk[d0 + 2][j];
            acc[0][0] = fmaf(q0, k0v, acc[0][0]);
            acc[0][1] = fmaf(q0, k1v, acc[0][1]);
            acc[0][2] = fmaf(q0, k2v, acc[0][2]);
            acc[1][0] = fmaf(q1, k0v, acc[1][0]);
            acc[1][1] = fmaf(q1, k1v, acc[1][1]);
            acc[1][2] = fmaf(q1, k2v, acc[1][2]);
            acc[2][0] = fmaf(q2, k0v, acc[2][0]);
            acc[2][1] = fmaf(q2, k1v, acc[2][1]);
            acc[2][2] = fmaf(q2, k2v, acc[2][2]);
        }
        __syncthreads();
    }
    float* op = g_attn_part + ((size_t)bh * NSPLIT + split) * CHD * CHD;
    #pragma unroll
    for (int a = 0; a < 3; a++)
        #pragma unroll
        for (int e = 0; e < 3; e++)
            op[(c0 + a) * CHD + d0 + e] = acc[a][e];
}

// ---------------- reduce partials + normalize + temperature + softmax -------
__global__ void __launch_bounds__(256) attn_softmax_kernel(const float* __restrict__ temp)
{
    const int bh = blockIdx.x;
    const int bb = bh >> 2, h = bh & 3;
    __shared__ float sA[CHD * CHD];
    const int tid = threadIdx.x;
    const float tpr = temp[h];
    for (int i = tid; i < CHD * CHD; i += 256) {
        float s = 0.f;
        #pragma unroll
        for (int sp = 0; sp < NSPLIT; sp++)
            s += g_attn_part[((size_t)bh * NSPLIT + sp) * CHD * CHD + i];
        int c = i / CHD, d = i - c * CHD;
        float nq = fmaxf(sqrtf(g_sumsq[bb * 384 + h * CHD + c]), 1e-12f);
        float nk = fmaxf(sqrtf(g_sumsq[bb * 384 + C1 + h * CHD + d]), 1e-12f);
        sA[i] = s / (nq * nk) * tpr;
    }
    __syncthreads();
    if (tid < CHD) {
        float mx = -1e30f;
        #pragma unroll
        for (int d = 0; d < CHD; d++) mx = fmaxf(mx, sA[tid * CHD + d]);
        float e[CHD];
        float ssum = 0.f;
        #pragma unroll
        for (int d = 0; d < CHD; d++) {
            e[d] = expf(sA[tid * CHD + d] - mx);
            ssum += e[d];
        }
        float inv = 1.f / ssum;
        #pragma unroll
        for (int d = 0; d < CHD; d++)
            g_attn[(size_t)bh * CHD * CHD + tid * CHD + d] = e[d] * inv;
    }
}

// ---------------- M[b] = proj_w @ blockdiag(attn[b]) ------------------------
__global__ void __launch_bounds__(256) buildM_kernel(const float* __restrict__ pw)
{
    int idx = blockIdx.x * 256 + threadIdx.x;
    int ci = idx % C1;
    int rest = idx / C1;
    int oc = rest % C1;
    int bb = rest / C1;
    int h = ci / CHD, d = ci % CHD;
    const float* a = g_attn + ((size_t)(bb * 4 + h)) * CHD * CHD + d;
    const float* w = pw + (size_t)oc * C1 + h * CHD;
    float s = 0.f;
    #pragma unroll
    for (int cc = 0; cc < CHD; cc++)
        s = fmaf(w[cc], a[(size_t)cc * CHD], s);
    g_M[((size_t)bb * C1 + oc) * C1 + ci] = s;
}

// ---------------- launch ----------------------------------------------------
extern "C" void kernel_launch(void* const* d_in, const int* in_sizes, int n_in,
                              void* d_out, int out_size)
{
    const float* x       = (const float*)d_in[0];
    const float* ln1_w   = (const float*)d_in[1];
    const float* ln1_b   = (const float*)d_in[2];
    const float* qkv_w   = (const float*)d_in[3];
    const float* qkv_b   = (const float*)d_in[4];
    const float* qkv_dww = (const float*)d_in[5];
    const float* qkv_dwb = (const float*)d_in[6];
    const float* temp    = (const float*)d_in[7];
    const float* prompt  = (const float*)d_in[8];
    const float* proj_w  = (const float*)d_in[9];
    const float* proj_b  = (const float*)d_in[10];
    const float* ln2_w   = (const float*)d_in[11];
    const float* ln2_b   = (const float*)d_in[12];
    const float* dw1_w   = (const float*)d_in[13];
    const float* dw1_b   = (const float*)d_in[14];
    const float* pm_w    = (const float*)d_in[15];
    const float* pm_b    = (const float*)d_in[16];
    const float* dw2_w   = (const float*)d_in[17];
    const float* dw2_b   = (const float*)d_in[18];
    const float* po_w    = (const float*)d_in[19];
    const float* po_b    = (const float*)d_in[20];
    float* out = (float*)d_out;

    void *pA, *pB, *pD, *pS, *pM, *pMu, *pIv, *pW2, *pSv, *pT;
    cudaGetSymbolAddress(&pA, g_bufA);
    cudaGetSymbolAddress(&pB, g_bufB);
    cudaGetSymbolAddress(&pD, g_bufD);
    cudaGetSymbolAddress(&pS, g_sumsq);
    cudaGetSymbolAddress(&pM, g_M);
    cudaGetSymbolAddress(&pMu, g_mu);
    cudaGetSymbolAddress(&pIv, g_inv);
    cudaGetSymbolAddress(&pW2, g_W2);
    cudaGetSymbolAddress(&pSv, g_S);
    cudaGetSymbolAddress(&pT, g_T);
    float* bufA = (float*)pA;
    float* bufB = (float*)pB;
    float* bufD = (float*)pD;
    float* Mptr = (float*)pM;
    float* muP  = (float*)pMu;
    float* ivP  = (float*)pIv;

    cudaFuncSetAttribute(gemm_tf32_kernel<1>, cudaFuncAttributeMaxDynamicSharedMemorySize, GEMM_SMEM);
    cudaFuncSetAttribute(gemm_tf32_kernel<2>, cudaFuncAttributeMaxDynamicSharedMemorySize, GEMM_SMEM);
    cudaFuncSetAttribute(gemm_tf32_kernel<3>, cudaFuncAttributeMaxDynamicSharedMemorySize, GEMM_SMEM);

    const int dwGrid = BATCH * C3 * (NPIX / 4) / 256;

    // ---- attention branch ----
    stats_kernel<<<BATCH * NPIX / 256, 256>>>(x, muP, ivP);
    prep_qkv_kernel<<<3, 192>>>(qkv_w, qkv_b, ln1_w, ln1_b);
    gemm_tf32_kernel<3><<<dim3(NPIX / 256, C3 / 64, BATCH), 256, GEMM_SMEM>>>(
        x, bufA, (float*)pW2, (float*)pT, nullptr, C3, C1, C1, 0, 0,
        (float*)pSv, muP, ivP);
    cudaMemsetAsync(pS, 0, BATCH * 2 * C1 * sizeof(float));
    dwconv_kernel<1, true, false><<<dwGrid, 256>>>(
        bufA, bufB, qkv_dww, qkv_dwb, prompt, nullptr, nullptr, nullptr, nullptr);
    qk_partial_kernel<<<dim3(32, NSPLIT), 256>>>(bufB);
    attn_softmax_kernel<<<32, 256>>>(temp);
    buildM_kernel<<<BATCH * C1 * C1 / 256, 256>>>(proj_w);
    // y1 = x + M @ v   (v = channels 384..575 of bufB)
    gemm_tf32_kernel<2><<<dim3(NPIX / 256, C1 / 64, BATCH), 256, GEMM_SMEM>>>(
        bufB, bufD, Mptr, proj_b, x, C1, C1, C3, 2 * C1, C1 * C1,
        nullptr, nullptr, nullptr);

    // ---- FFN branch ----
    stats_kernel<<<BATCH * NPIX / 256, 256>>>(bufD, muP, ivP);
    dwconv_kernel<3, false, true><<<dwGrid, 256>>>(
        bufD, bufA, dw1_w, dw1_b, nullptr, muP, ivP, ln2_w, ln2_b);
    gemm_tf32_kernel<1><<<dim3(NPIX / 256, C3 / 64, BATCH), 256, GEMM_SMEM>>>(
        bufA, bufB, pm_w, pm_b, nullptr, C3, C3, C3, 0, 0,
        nullptr, nullptr, nullptr);
    dwconv_kernel<1, false, false><<<dwGrid, 256>>>(
        bufB, bufA, dw2_w, dw2_b, nullptr, nullptr, nullptr, nullptr, nullptr);
    gemm_tf32_kernel<2><<<dim3(NPIX / 256, C1 / 64, BATCH), 256, GEMM_SMEM>>>(
        bufA, out, po_w, po_b, bufD, C1, C3, C3, 0, 0,
        nullptr, nullptr, nullptr);
}

// round 10
// speedup vs baseline: 1.1127x; 1.1127x over previous
#include <cuda_runtime.h>
#include <math.h>
#include <stdint.h>

#define BATCH 8
#define C1    192
#define C3    576
#define HEADS 4
#define CHD   48
#define HH    128
#define WW    128
#define NPIX  16384
#define EPSV  1e-5f
#define NSPLIT 32

// ---------------- scratch (static device allocations) -----------------------
__device__ float g_bufA[BATCH * C3 * NPIX];
__device__ float g_bufB[BATCH * C3 * NPIX];
__device__ float g_bufC[BATCH * C1 * NPIX];
__device__ float g_bufD[BATCH * C1 * NPIX];
__device__ float g_sumsq[BATCH * 2 * C1];
__device__ float g_attn_part[32 * NSPLIT * CHD * CHD];
__device__ float g_attn[32 * CHD * CHD];
__device__ float g_M[BATCH * C1 * C1];      // fused proj_w @ blockdiag(attn)

// ---------------- LayerNorm over channel dim (per pixel) --------------------
__global__ void __launch_bounds__(256) ln_kernel(
    const float* __restrict__ x, float* __restrict__ out,
    const float* __restrict__ w, const float* __restrict__ b)
{
    int idx = blockIdx.x * 256 + threadIdx.x;
    int bb = idx >> 14;
    int p  = idx & (NPIX - 1);
    const float* xp = x + (size_t)bb * C1 * NPIX + p;
    float s = 0.f, s2 = 0.f;
    #pragma unroll 4
    for (int c = 0; c < C1; c++) {
        float v = xp[(size_t)c * NPIX];
        s += v; s2 = fmaf(v, v, s2);
    }
    float mu  = s * (1.f / C1);
    float var = fmaxf(s2 * (1.f / C1) - mu * mu, 0.f);
    float inv = rsqrtf(var + EPSV);
    float* op = out + (size_t)bb * C1 * NPIX + p;
    #pragma unroll 4
    for (int c = 0; c < C1; c++) {
        op[(size_t)c * NPIX] = (xp[(size_t)c * NPIX] - mu) * inv * w[c] + b[c];
    }
}

// ---------------- tf32 tensor-core GEMM with cp.async double buffering ------
// FUSE: 0 = bias, 1 = bias+GELU, 2 = bias+residual
#define ASTRIDE 36
#define BSTRIDE 264
#define ASTAGE  (64 * ASTRIDE)
#define BSTAGE  (32 * BSTRIDE)
#define GEMM_SMEM ((2 * (ASTAGE + BSTAGE)) * 4)

__device__ __forceinline__ void mma_tf32(float* c, const uint32_t* a, const uint32_t* b) {
    asm volatile(
        "mma.sync.aligned.m16n8k8.row.col.f32.tf32.tf32.f32 "
        "{%0,%1,%2,%3}, {%4,%5,%6,%7}, {%8,%9}, {%0,%1,%2,%3};\n"
        : "+f"(c[0]), "+f"(c[1]), "+f"(c[2]), "+f"(c[3])
        : "r"(a[0]), "r"(a[1]), "r"(a[2]), "r"(a[3]), "r"(b[0]), "r"(b[1]));
}
__device__ __forceinline__ void cp16(void* s, const void* g) {
    uint32_t sa = (uint32_t)__cvta_generic_to_shared(s);
    asm volatile("cp.async.cg.shared.global [%0], [%1], 16;\n" :: "r"(sa), "l"(g));
}

template<int FUSE>
__global__ void __launch_bounds__(256) gemm_tf32_kernel(
    const float* __restrict__ in, float* __restrict__ out,
    const float* __restrict__ W, const float* __restrict__ bias,
    const float* __restrict__ resid, int M, int K,
    int in_bstride, int in_coff, int w_bstride)
{
    extern __shared__ float dsm[];
    float* As = dsm;
    float* Bs = dsm + 2 * ASTAGE;

    const int tid  = threadIdx.x;
    const int lane = tid & 31;
    const int wrp  = tid >> 5;
    const int n0   = blockIdx.x * 256;
    const int m0   = blockIdx.y * 64;
    const int bb   = blockIdx.z;
    const float* inb = in + ((size_t)bb * in_bstride + in_coff) * NPIX + n0;
    const float* Wb  = W + (size_t)bb * w_bstride;

    const int am = tid >> 2;
    const int ak = (tid & 3) * 8;

    float acc[4][4][4];
    #pragma unroll
    for (int mt = 0; mt < 4; mt++)
        #pragma unroll
        for (int nt = 0; nt < 4; nt++)
            #pragma unroll
            for (int i = 0; i < 4; i++) acc[mt][nt][i] = 0.f;

    auto load_stage = [&](int k0, int st) {
        const float* wr = Wb + (size_t)(m0 + am) * K + k0 + ak;
        float* ad = As + st * ASTAGE + am * ASTRIDE + ak;
        cp16(ad, wr);
        cp16(ad + 4, wr + 4);
        #pragma unroll
        for (int i = 0; i < 8; i++) {
            int l  = tid + i * 256;
            int r  = l >> 6;
            int c4 = (l & 63) * 4;
            cp16(Bs + st * BSTAGE + r * BSTRIDE + c4,
                 inb + (size_t)(k0 + r) * NPIX + c4);
        }
    };

    load_stage(0, 0);
    asm volatile("cp.async.commit_group;\n" ::);

    for (int k0 = 0; k0 < K; k0 += 32) {
        int st = (k0 >> 5) & 1;
        if (k0 + 32 < K) {
            load_stage(k0 + 32, st ^ 1);
            asm volatile("cp.async.commit_group;\n" ::);
            asm volatile("cp.async.wait_group 1;\n" ::);
        } else {
            asm volatile("cp.async.wait_all;\n" ::);
        }
        __syncthreads();

        const uint32_t* Au = (const uint32_t*)(As + st * ASTAGE);
        const uint32_t* Bu = (const uint32_t*)(Bs + st * BSTAGE);
        #pragma unroll
        for (int kk = 0; kk < 32; kk += 8) {
            const int kr   = kk + (lane & 3);
            const int mrow = lane >> 2;
            uint32_t a[4][4], b[4][2];
            #pragma unroll
            for (int mt = 0; mt < 4; mt++) {
                int mb = mt * 16 + mrow;
                a[mt][0] = Au[mb * ASTRIDE + kr];
                a[mt][1] = Au[(mb + 8) * ASTRIDE + kr];
                a[mt][2] = Au[mb * ASTRIDE + kr + 4];
                a[mt][3] = Au[(mb + 8) * ASTRIDE + kr + 4];
            }
            #pragma unroll
            for (int nt = 0; nt < 4; nt++) {
                int nc = wrp * 32 + nt * 8 + (lane >> 2);
                b[nt][0] = Bu[kr * BSTRIDE + nc];
                b[nt][1] = Bu[(kr + 4) * BSTRIDE + nc];
            }
            #pragma unroll
            for (int mt = 0; mt < 4; mt++)
                #pragma unroll
                for (int nt = 0; nt < 4; nt++)
                    mma_tf32(acc[mt][nt], a[mt], b[nt]);
        }
        __syncthreads();
    }

    #pragma unroll
    for (int mt = 0; mt < 4; mt++) {
        int r0 = m0 + mt * 16 + (lane >> 2);
        int r1 = r0 + 8;
        float bv0 = __ldg(&bias[r0]);
        float bv1 = __ldg(&bias[r1]);
        float* o0 = out + ((size_t)bb * M + r0) * NPIX + n0;
        float* o1 = out + ((size_t)bb * M + r1) * NPIX + n0;
        #pragma unroll
        for (int nt = 0; nt < 4; nt++) {
            int col = wrp * 32 + nt * 8 + (lane & 3) * 2;
            float v0 = acc[mt][nt][0] + bv0;
            float v1 = acc[mt][nt][1] + bv0;
            float v2 = acc[mt][nt][2] + bv1;
            float v3 = acc[mt][nt][3] + bv1;
            if (FUSE == 1) {
                v0 = 0.5f * v0 * (1.f + erff(v0 * 0.70710678118654752f));
                v1 = 0.5f * v1 * (1.f + erff(v1 * 0.70710678118654752f));
                v2 = 0.5f * v2 * (1.f + erff(v2 * 0.70710678118654752f));
                v3 = 0.5f * v3 * (1.f + erff(v3 * 0.70710678118654752f));
            }
            if (FUSE == 2) {
                const float* rr0 = resid + ((size_t)bb * M + r0) * NPIX + n0;
                const float* rr1 = resid + ((size_t)bb * M + r1) * NPIX + n0;
                float2 q0 = *(const float2*)(rr0 + col);
                float2 q1 = *(const float2*)(rr1 + col);
                v0 += q0.x; v1 += q0.y; v2 += q1.x; v3 += q1.y;
            }
            *(float2*)(o0 + col) = make_float2(v0, v1);
            *(float2*)(o1 + col) = make_float2(v2, v3);
        }
    }
}

// ---------------- depthwise / grouped 3x3 conv: warp-per-row + shuffle halo -
// Each warp owns one image row of one channel: lane -> 4 px. Left/right
// neighbors come from __shfl, eliminating all scalar edge loads.
template<int RATIO, bool SUMSQ>
__global__ void __launch_bounds__(256) dwconv_kernel(
    const float* __restrict__ in, float* __restrict__ out,
    const float* __restrict__ wt, const float* __restrict__ bias,
    const float* __restrict__ prompt)
{
    const int warp = threadIdx.x >> 5;
    const int lane = threadIdx.x & 31;
    int rowIdx = blockIdx.x * 8 + warp;       // over BATCH*C3*HH
    int y    = rowIdx & (HH - 1);
    int rest = rowIdx >> 7;
    int c    = rest % C3;
    int bb   = rest / C3;
    const int x0 = lane * 4;

    const float* ip = in + ((size_t)bb * (C3 / RATIO) + c / RATIO) * NPIX;
    const float* wp = wt + c * 9;
    float w[9];
    #pragma unroll
    for (int i = 0; i < 9; i++) w[i] = __ldg(&wp[i]);

    float bv = __ldg(&bias[c]);
    if (prompt != nullptr)
        bv += __ldg(&prompt[((c % C1) / CHD) * CHD + (c % CHD)]);
    float o0 = bv, o1 = bv, o2 = bv, o3 = bv;

    #pragma unroll
    for (int dy = -1; dy <= 1; dy++) {
        int yy = y + dy;
        if ((unsigned)yy < (unsigned)HH) {
            float4 m = *(const float4*)(ip + yy * WW + x0);
            float L = __shfl_up_sync(0xffffffffu, m.w, 1);
            float R = __shfl_down_sync(0xffffffffu, m.x, 1);
            if (lane == 0)  L = 0.f;
            if (lane == 31) R = 0.f;
            float w0 = w[(dy + 1) * 3 + 0];
            float w1 = w[(dy + 1) * 3 + 1];
            float w2 = w[(dy + 1) * 3 + 2];
            o0 = fmaf(w0, L,   fmaf(w1, m.x, fmaf(w2, m.y, o0)));
            o1 = fmaf(w0, m.x, fmaf(w1, m.y, fmaf(w2, m.z, o1)));
            o2 = fmaf(w0, m.y, fmaf(w1, m.z, fmaf(w2, m.w, o2)));
            o3 = fmaf(w0, m.z, fmaf(w1, m.w, fmaf(w2, R,   o3)));
        }
    }
    *(float4*)(out + ((size_t)bb * C3 + c) * NPIX + y * WW + x0) =
        make_float4(o0, o1, o2, o3);

    if (SUMSQ) {
        // all 8 warps of a block are rows of the SAME channel (128 % 8 == 0)
        float ssq = o0 * o0 + o1 * o1 + o2 * o2 + o3 * o3;
        __shared__ float red[8];
        #pragma unroll
        for (int off = 16; off > 0; off >>= 1)
            ssq += __shfl_down_sync(0xffffffffu, ssq, off);
        if (lane == 0) red[warp] = ssq;
        __syncthreads();
        if (threadIdx.x == 0 && c < 2 * C1) {
            float t = 0.f;
            #pragma unroll
            for (int wv = 0; wv < 8; wv++) t += red[wv];
            atomicAdd(&g_sumsq[bb * 2 * C1 + c], t);
        }
    }
}

// ---------------- QK^T partial GEMM (48x48, split-K over spatial) -----------
__global__ void __launch_bounds__(256) qk_partial_kernel(const float* __restrict__ qkv)
{
    const int bh = blockIdx.x, split = blockIdx.y;
    const int bb = bh >> 2, h = bh & 3;
    const int CSPL = NPIX / NSPLIT;   // 512
    const float* qb = qkv + ((size_t)bb * C3 + h * CHD) * NPIX + split * CSPL;
    const float* kb = qkv + ((size_t)bb * C3 + C1 + h * CHD) * NPIX + split * CSPL;
    __shared__ float sq[CHD][33];
    __shared__ float sk[CHD][33];
    const int tid = threadIdx.x;
    const int c0 = (tid >> 4) * 3, d0 = (tid & 15) * 3;
    float acc[3][3] = {};

    for (int n0 = 0; n0 < CSPL; n0 += 32) {
        for (int i = tid; i < CHD * 32; i += 256) {
            int c = i >> 5, j = i & 31;
            sq[c][j] = qb[(size_t)c * NPIX + n0 + j];
            sk[c][j] = kb[(size_t)c * NPIX + n0 + j];
        }
        __syncthreads();
        #pragma unroll
        for (int j = 0; j < 32; j++) {
            float q0 = sq[c0][j], q1 = sq[c0 + 1][j], q2 = sq[c0 + 2][j];
            float k0v = sk[d0][j], k1v = sk[d0 + 1][j], k2v = sk[d0 + 2][j];
            acc[0][0] = fmaf(q0, k0v, acc[0][0]);
            acc[0][1] = fmaf(q0, k1v, acc[0][1]);
            acc[0][2] = fmaf(q0, k2v, acc[0][2]);
            acc[1][0] = fmaf(q1, k0v, acc[1][0]);
            acc[1][1] = fmaf(q1, k1v, acc[1][1]);
            acc[1][2] = fmaf(q1, k2v, acc[1][2]);
            acc[2][0] = fmaf(q2, k0v, acc[2][0]);
            acc[2][1] = fmaf(q2, k1v, acc[2][1]);
            acc[2][2] = fmaf(q2, k2v, acc[2][2]);
        }
        __syncthreads();
    }
    float* op = g_attn_part + ((size_t)bh * NSPLIT + split) * CHD * CHD;
    #pragma unroll
    for (int a = 0; a < 3; a++)
        #pragma unroll
        for (int e = 0; e < 3; e++)
            op[(c0 + a) * CHD + d0 + e] = acc[a][e];
}

// ---------------- reduce partials + normalize + temperature + softmax -------
__global__ void __launch_bounds__(256) attn_softmax_kernel(const float* __restrict__ temp)
{
    const int bh = blockIdx.x;
    const int bb = bh >> 2, h = bh & 3;
    __shared__ float sA[CHD * CHD];
    const int tid = threadIdx.x;
    const float tpr = temp[h];
    for (int i = tid; i < CHD * CHD; i += 256) {
        float s = 0.f;
        #pragma unroll
        for (int sp = 0; sp < NSPLIT; sp++)
            s += g_attn_part[((size_t)bh * NSPLIT + sp) * CHD * CHD + i];
        int c = i / CHD, d = i - c * CHD;
        float nq = fmaxf(sqrtf(g_sumsq[bb * 384 + h * CHD + c]), 1e-12f);
        float nk = fmaxf(sqrtf(g_sumsq[bb * 384 + C1 + h * CHD + d]), 1e-12f);
        sA[i] = s / (nq * nk) * tpr;
    }
    __syncthreads();
    if (tid < CHD) {
        float mx = -1e30f;
        #pragma unroll
        for (int d = 0; d < CHD; d++) mx = fmaxf(mx, sA[tid * CHD + d]);
        float e[CHD];
        float ssum = 0.f;
        #pragma unroll
        for (int d = 0; d < CHD; d++) {
            e[d] = expf(sA[tid * CHD + d] - mx);
            ssum += e[d];
        }
        float inv = 1.f / ssum;
        #pragma unroll
        for (int d = 0; d < CHD; d++)
            g_attn[(size_t)bh * CHD * CHD + tid * CHD + d] = e[d] * inv;
    }
}

// ---------------- M[b] = proj_w @ blockdiag(attn[b]) ------------------------
__global__ void __launch_bounds__(256) buildM_kernel(const float* __restrict__ pw)
{
    int idx = blockIdx.x * 256 + threadIdx.x;
    int ci = idx % C1;
    int rest = idx / C1;
    int oc = rest % C1;
    int bb = rest / C1;
    int h = ci / CHD, d = ci % CHD;
    const float* a = g_attn + ((size_t)(bb * 4 + h)) * CHD * CHD + d;
    const float* w = pw + (size_t)oc * C1 + h * CHD;
    float s = 0.f;
    #pragma unroll
    for (int cc = 0; cc < CHD; cc++)
        s = fmaf(w[cc], a[(size_t)cc * CHD], s);
    g_M[((size_t)bb * C1 + oc) * C1 + ci] = s;
}

// ---------------- launch ----------------------------------------------------
extern "C" void kernel_launch(void* const* d_in, const int* in_sizes, int n_in,
                              void* d_out, int out_size)
{
    const float* x       = (const float*)d_in[0];
    const float* ln1_w   = (const float*)d_in[1];
    const float* ln1_b   = (const float*)d_in[2];
    const float* qkv_w   = (const float*)d_in[3];
    const float* qkv_b   = (const float*)d_in[4];
    const float* qkv_dww = (const float*)d_in[5];
    const float* qkv_dwb = (const float*)d_in[6];
    const float* temp    = (const float*)d_in[7];
    const float* prompt  = (const float*)d_in[8];
    const float* proj_w  = (const float*)d_in[9];
    const float* proj_b  = (const float*)d_in[10];
    const float* ln2_w   = (const float*)d_in[11];
    const float* ln2_b   = (const float*)d_in[12];
    const float* dw1_w   = (const float*)d_in[13];
    const float* dw1_b   = (const float*)d_in[14];
    const float* pm_w    = (const float*)d_in[15];
    const float* pm_b    = (const float*)d_in[16];
    const float* dw2_w   = (const float*)d_in[17];
    const float* dw2_b   = (const float*)d_in[18];
    const float* po_w    = (const float*)d_in[19];
    const float* po_b    = (const float*)d_in[20];
    float* out = (float*)d_out;

    void *pA, *pB, *pC, *pD, *pS, *pM;
    cudaGetSymbolAddress(&pA, g_bufA);
    cudaGetSymbolAddress(&pB, g_bufB);
    cudaGetSymbolAddress(&pC, g_bufC);
    cudaGetSymbolAddress(&pD, g_bufD);
    cudaGetSymbolAddress(&pS, g_sumsq);
    cudaGetSymbolAddress(&pM, g_M);
    float* bufA = (float*)pA;
    float* bufB = (float*)pB;
    float* bufC = (float*)pC;
    float* bufD = (float*)pD;
    float* Mptr = (float*)pM;

    cudaFuncSetAttribute(gemm_tf32_kernel<0>, cudaFuncAttributeMaxDynamicSharedMemorySize, GEMM_SMEM);
    cudaFuncSetAttribute(gemm_tf32_kernel<1>, cudaFuncAttributeMaxDynamicSharedMemorySize, GEMM_SMEM);
    cudaFuncSetAttribute(gemm_tf32_kernel<2>, cudaFuncAttributeMaxDynamicSharedMemorySize, GEMM_SMEM);

    const int dwGrid = BATCH * C3 * HH / 8;   // warp-per-row, 8 warps/block

    // ---- attention branch ----
    ln_kernel<<<BATCH * NPIX / 256, 256>>>(x, bufC, ln1_w, ln1_b);
    gemm_tf32_kernel<0><<<dim3(NPIX / 256, C3 / 64, BATCH), 256, GEMM_SMEM>>>(
        bufC, bufA, qkv_w, qkv_b, nullptr, C3, C1, C1, 0, 0);
    cudaMemsetAsync(pS, 0, BATCH * 2 * C1 * sizeof(float));
    dwconv_kernel<1, true><<<dwGrid, 256>>>(bufA, bufB, qkv_dww, qkv_dwb, prompt);
    qk_partial_kernel<<<dim3(32, NSPLIT), 256>>>(bufB);
    attn_softmax_kernel<<<32, 256>>>(temp);
    buildM_kernel<<<BATCH * C1 * C1 / 256, 256>>>(proj_w);
    // y1 = x + M @ v   (v = channels 384..575 of bufB)
    gemm_tf32_kernel<2><<<dim3(NPIX / 256, C1 / 64, BATCH), 256, GEMM_SMEM>>>(
        bufB, bufD, Mptr, proj_b, x, C1, C1, C3, 2 * C1, C1 * C1);

    // ---- FFN branch ----
    ln_kernel<<<BATCH * NPIX / 256, 256>>>(bufD, bufC, ln2_w, ln2_b);
    dwconv_kernel<3, false><<<dwGrid, 256>>>(bufC, bufA, dw1_w, dw1_b, nullptr);
    gemm_tf32_kernel<1><<<dim3(NPIX / 256, C3 / 64, BATCH), 256, GEMM_SMEM>>>(
        bufA, bufB, pm_w, pm_b, nullptr, C3, C3, C3, 0, 0);
    dwconv_kernel<1, false><<<dwGrid, 256>>>(bufB, bufA, dw2_w, dw2_b, nullptr);
    gemm_tf32_kernel<2><<<dim3(NPIX / 256, C1 / 64, BATCH), 256, GEMM_SMEM>>>(
        bufA, out, po_w, po_b, bufD, C1, C3, C3, 0, 0);
}